// round 13
// baseline (speedup 1.0000x reference)
#include <cuda_runtime.h>

#define BB 16
#define LL 2048
#define VV 64
#define KBT 512             // kB threads: 128 t x 4 vgroups
#define NBLK 16             // kB blocks per batch (4 windows of 32 t each)
#define PADL 2560           // padded position-list length (64 classes, 8-aligned)

// Scratch (device globals)
__device__ float g_E[(size_t)BB * VV * LL];      // exp(P[b,c,t]), 8 MB
__device__ int g_pos[BB * PADL];                 // positions sorted by class, 8-aligned segs
__device__ int g_starts[BB * (VV + 1)];          // padded segment starts (8-aligned)
__device__ int g_cnt[BB * VV];                   // real counts per class

// degree-7 Taylor exp; |x| small here -> rel err < 1e-9
__device__ __forceinline__ float exp_poly(float x) {
    float r = 1.f / 5040.f;
    r = fmaf(r, x, 1.f / 720.f);
    r = fmaf(r, x, 1.f / 120.f);
    r = fmaf(r, x, 1.f / 24.f);
    r = fmaf(r, x, 1.f / 6.f);
    r = fmaf(r, x, 0.5f);
    r = fmaf(r, x, 1.f);
    r = fmaf(r, x, 1.f);
    return r;
}

// window base (in 32-t units) for window-slot wi of block bx:
// {bx, 31-bx, 32+bx, 63-bx} -> per-block total work is EXACTLY equal.
__device__ __forceinline__ int win32(int wi, int bx) {
    int base = (wi & 2) ? 32 : 0;
    return (wi & 1) ? (base + 31 - bx) : (base + bx);
}

// ---------------------------------------------------------------------------
// kS: stable counting sort of positions by class (match_any), 8-aligned
// padded segments, sentinel LL. Proven ~7.5us.
// ---------------------------------------------------------------------------
__global__ void __launch_bounds__(1024) kS(const int* __restrict__ idx) {
    __shared__ int cnt[64][65];
    __shared__ int stot[64];
    __shared__ int pstart[65];

    const int b = blockIdx.x;
    const int tid = threadIdx.x;
    const int lane = tid & 31;
    const int wid = tid >> 5;

    for (int i = tid; i < 64 * 65; i += 1024) ((int*)cnt)[i] = 0;
    __syncthreads();

    int v0, lr0, v1, lr1;
    {
        v0 = idx[b * LL + tid];
        unsigned m = __match_any_sync(0xffffffffu, v0);
        lr0 = __popc(m & ((1u << lane) - 1u));
        if (lr0 == 0) cnt[tid >> 5][v0] = __popc(m);
    }
    {
        int j = tid + 1024;
        v1 = idx[b * LL + j];
        unsigned m = __match_any_sync(0xffffffffu, v1);
        lr1 = __popc(m & ((1u << lane) - 1u));
        if (lr1 == 0) cnt[j >> 5][v1] = __popc(m);
    }
    __syncthreads();

#pragma unroll
    for (int cc = 0; cc < 2; ++cc) {
        int c = wid * 2 + cc;
        int a = cnt[2 * lane][c];
        int d = cnt[2 * lane + 1][c];
        int s = a + d;
        int x = s;
#pragma unroll
        for (int off = 1; off < 32; off <<= 1) {
            int y = __shfl_up_sync(0xffffffffu, x, off);
            if (lane >= off) x += y;
        }
        int e = x - s;
        cnt[2 * lane][c] = e;
        cnt[2 * lane + 1][c] = e + a;
        if (lane == 31) stot[c] = x;
    }
    __syncthreads();

    if (wid == 0) {
        int t0c = (stot[2 * lane] + 7) & ~7;
        int t1c = (stot[2 * lane + 1] + 7) & ~7;
        int s = t0c + t1c;
        int x = s;
#pragma unroll
        for (int off = 1; off < 32; off <<= 1) {
            int y = __shfl_up_sync(0xffffffffu, x, off);
            if (lane >= off) x += y;
        }
        int e = x - s;
        pstart[2 * lane] = e;
        pstart[2 * lane + 1] = e + t0c;
        if (lane == 31) pstart[64] = x;
    }
    __syncthreads();

    g_pos[b * PADL + pstart[v0] + cnt[tid >> 5][v0] + lr0] = tid;
    g_pos[b * PADL + pstart[v1] + cnt[(tid + 1024) >> 5][v1] + lr1] = tid + 1024;

    if (tid < 64) {
        for (int i = pstart[tid] + stot[tid]; i < pstart[tid + 1]; ++i)
            g_pos[b * PADL + i] = LL;   // sentinel
        g_cnt[b * 64 + tid] = stot[tid];
        g_starts[b * 65 + tid] = pstart[tid];
        if (tid == 0) g_starts[b * 65 + 64] = pstart[64];
    }
}

// ---------------------------------------------------------------------------
// kB: 256 blocks (one wave at 2/SM), 512 threads. (R12 verbatim)
// ---------------------------------------------------------------------------
__global__ void __launch_bounds__(KBT, 2) kB(const float* __restrict__ Wq,
                                             const float* __restrict__ v_emb) {
    extern __shared__ __align__(16) char smraw[];
    float* s_wg   = (float*)smraw;                       // 2*LL: guard zeros + w
    float* s_wq   = s_wg + 2 * LL;                       // 4096 f
    float* s_l1   = s_wq + VV * VV;                      // VV*128 = 8192 f
    float* s_invd = s_l1 + VV * 128;                     // 128 (indexed by tt)
    int*   s_pos  = (int*)(s_invd + 128);                // PADL (byte offsets p<<2)
    int*   s_start = s_pos + PADL;                       // 66
    int*   s_cut   = s_start + 66;                       // 4*64 (per window, class)
    float* s_cbp   = (float*)(s_cut + 256);              // 64 inclusive chunk prefix
    float* s_wt    = s_cbp + 64;                         // 2
    float* s_w = s_wg + LL;

    const int bx  = blockIdx.x;                          // 0..15
    const int b   = blockIdx.y;
    const int tid = threadIdx.x;
    const int lane = tid & 31;

    for (int i = tid; i < LL; i += KBT) { s_wg[i] = 0.f; s_w[i] = exp_poly(v_emb[i]); }
    for (int i = tid; i < VV * VV; i += KBT) s_wq[i] = Wq[i];
    {   // positions staged pre-scaled by 4 (byte offsets)
        const int4* src = (const int4*)(g_pos + b * PADL);
        int4* dst = (int4*)s_pos;
        for (int i = tid; i < PADL / 4; i += KBT) {
            int4 p = src[i];
            p.x <<= 2; p.y <<= 2; p.z <<= 2; p.w <<= 2;
            dst[i] = p;
        }
    }
    for (int i = tid; i <= VV; i += KBT) s_start[i] = g_starts[b * 65 + i];
    __syncthreads();

    // cutoffs: tid<256 -> (wi = tid>>6, v = tid&63)
    if (tid < 256) {
        const int wi = tid >> 6;
        const int v  = tid & 63;
        const int te4 = ((win32(wi, bx) + 1) * 32) << 2;
        int lo = s_start[v], hi = s_start[v + 1];
        while (lo < hi) {
            int mid = (lo + hi) >> 1;
            if (s_pos[mid] < te4) lo = mid + 1; else hi = mid;
        }
        s_cut[tid] = lo;
    }
    // 32-elem chunk sums of w (64 chunks), scanned with 2 warps + combine
    float cbx = 0.f;
    if (tid < 64) {
        float cb = 0.f;
        const int cb0 = tid * 32;
#pragma unroll
        for (int m = 0; m < 32; ++m) cb += s_w[cb0 + m];
        cbx = cb;
#pragma unroll
        for (int off = 1; off < 32; off <<= 1) {
            float y = __shfl_up_sync(0xffffffffu, cbx, off);
            if (lane >= off) cbx += y;
        }
        if (lane == 31) s_wt[tid >> 5] = cbx;
    }
    __syncthreads();
    if (tid < 64) s_cbp[tid] = cbx + ((tid >> 5) ? s_wt[0] : 0.f);
    __syncthreads();
    if (tid < 128) {
        const int wi = tid >> 5;
        const int wb = win32(wi, bx);           // chunk index = window base/32
        float sv = s_w[wb * 32 + lane];
#pragma unroll
        for (int off = 1; off < 32; off <<= 1) {
            float y = __shfl_up_sync(0xffffffffu, sv, off);
            if (lane >= off) sv += y;
        }
        float D = (wb ? s_cbp[wb - 1] : 0.f) + sv;
        s_invd[tid] = 1.0f / D;
    }
    __syncthreads();

    // --- Phase A: warp w -> (window wi = w>>2, vgroup vg = w&3) ---
    {
        const int w  = tid >> 5;
        const int wi = w >> 2;
        const int vg = w & 3;
        const int tt = wi * 32 + lane;
        const int t  = win32(wi, bx) * 32 + lane;
        const float invd = s_invd[tt];
        const char* wtb = (const char*)(s_w + t);   // w[t-p] at wtb - 4p
        const int4* P = (const int4*)s_pos;
#pragma unroll
        for (int vs = 0; vs < 16; ++vs) {
            const int v = vg + 4 * vs;
            int g    = s_start[v] >> 3;             // segments 8-aligned
            int gend = (s_cut[wi * 64 + v] + 7) >> 3;  // tail extras hit zero guard
            float a0 = 0.f, a1 = 0.f, a2 = 0.f, a3 = 0.f;
#pragma unroll 2
            for (; g < gend; ++g) {
                int4 pa = P[2 * g];
                int4 pb = P[2 * g + 1];
                a0 += *(const float*)(wtb - pa.x);
                a1 += *(const float*)(wtb - pa.y);
                a2 += *(const float*)(wtb - pa.z);
                a3 += *(const float*)(wtb - pa.w);
                a0 += *(const float*)(wtb - pb.x);
                a1 += *(const float*)(wtb - pb.y);
                a2 += *(const float*)(wtb - pb.z);
                a3 += *(const float*)(wtb - pb.w);
            }
            s_l1[v * 128 + tt] = ((a0 + a1) + (a2 + a3)) * invd;
        }
    }
    __syncthreads();

    // --- Phase B: 16 classes per thread (tt = tid&127, cg = tid>>7), FFMA2 ---
    const int tt = tid & 127;
    const int cg = tid >> 7;            // 0..3
    unsigned long long acc[8];
#pragma unroll
    for (int i = 0; i < 8; ++i) acc[i] = 0ull;

#pragma unroll 4
    for (int v = 0; v < VV; ++v) {
        float lv = s_l1[v * 128 + tt];
        unsigned long long lv2;
        asm("mov.b64 %0, {%1, %1};" : "=l"(lv2) : "r"(__float_as_uint(lv)));
        const double2* q = (const double2*)&s_wq[v * VV + cg * 16];
#pragma unroll
        for (int i = 0; i < 4; ++i) {
            double2 qq = q[i];
            unsigned long long qa = __double_as_longlong(qq.x);
            unsigned long long qb = __double_as_longlong(qq.y);
            asm("fma.rn.f32x2 %0, %1, %2, %0;" : "+l"(acc[2 * i])     : "l"(qa), "l"(lv2));
            asm("fma.rn.f32x2 %0, %1, %2, %0;" : "+l"(acc[2 * i + 1]) : "l"(qb), "l"(lv2));
        }
    }

    // Epilogue: E = exp(P), coalesced over t within each window
    const int t_out = win32(tt >> 5, bx) * 32 + (tt & 31);
    float* eb = g_E + ((size_t)b * VV + cg * 16) * LL + t_out;
#pragma unroll
    for (int i = 0; i < 8; ++i) {
        unsigned lo, hi;
        asm("mov.b64 {%0, %1}, %2;" : "=r"(lo), "=r"(hi) : "l"(acc[i]));
        eb[(size_t)(2 * i) * LL]     = exp_poly(__uint_as_float(lo));
        eb[(size_t)(2 * i + 1) * LL] = exp_poly(__uint_as_float(hi));
    }
}

// ---------------------------------------------------------------------------
// kC: per (b,c), 128 threads (R12 verbatim).
// ---------------------------------------------------------------------------
__global__ void __launch_bounds__(128) kC(const float* __restrict__ Wv,
                                          float* __restrict__ out) {
    __shared__ __align__(16) float sE[LL];
    __shared__ float sP[LL];
    __shared__ __align__(16) int spos[PADL];
    __shared__ int sstart[VV + 2];
    __shared__ int scnt[VV];
    __shared__ float wtot[4];

    const int c   = blockIdx.x;
    const int b   = blockIdx.y;
    const int tid = threadIdx.x;
    const int lane = tid & 31, w = tid >> 5;

    const float* Ep = g_E + ((size_t)b * VV + c) * LL;
    {
        const float4* src = (const float4*)Ep;
        float4* dst = (float4*)sE;
        for (int i = tid; i < LL / 4; i += 128) dst[i] = src[i];
        const int4* psrc = (const int4*)(g_pos + b * PADL);
        int4* pdst = (int4*)spos;
        for (int i = tid; i < PADL / 4; i += 128) pdst[i] = psrc[i];
    }
    for (int i = tid; i <= VV; i += 128) sstart[i] = g_starts[b * 65 + i];
    if (tid < 64) scnt[tid] = g_cnt[b * 64 + tid];
    __syncthreads();

    const int s0 = tid * 16;
    float tot = 0.f;
#pragma unroll
    for (int m = 0; m < 16; ++m) tot += sE[s0 + m];
    float x = tot;
#pragma unroll
    for (int off = 1; off < 32; off <<= 1) {
        float y = __shfl_up_sync(0xffffffffu, x, off);
        if (lane >= off) x += y;
    }
    if (lane == 31) wtot[w] = x;
    __syncthreads();
    float base = x - tot;
    for (int j = 0; j < w; ++j) base += wtot[j];
#pragma unroll
    for (int m = 0; m < 16; ++m) { base += sE[s0 + m]; sP[s0 + m] = base; }
    __syncthreads();

    if (tid < 64) {
        const float wv00 = Wv[0];
        float* ob = out + (size_t)b * LL * VV;

        int ptr  = sstart[tid];
        const int pend = ptr + scnt[tid];
        float acc = 0.f;

        const int cbeg = sstart[c];
        const int cend = cbeg + scnt[c];
        for (int k = cbeg; k < cend; ++k) {
            const int tk = spos[k];
            while (ptr < pend) {
                int p = spos[ptr];
                if (p > tk) break;
                acc += sE[p];
                ++ptr;
            }
            float sc = __fdividef(wv00, sP[tk]);
            ob[(size_t)tk * VV + tid] = acc * sc;
        }
    }
}

extern "C" void kernel_launch(void* const* d_in, const int* in_sizes, int n_in,
                              void* d_out, int out_size) {
    const int*   idx   = (const int*)d_in[0];
    const float* Wq    = (const float*)d_in[1];
    const float* Wv    = (const float*)d_in[2];
    const float* v_emb = (const float*)d_in[3];
    float* out = (float*)d_out;

    size_t smemB = (size_t)(2 * LL) * 4      // guard + w
                 + (size_t)VV * VV * 4       // wq
                 + (size_t)VV * 128 * 4      // l1
                 + 128 * 4                   // invd
                 + (size_t)PADL * 4          // pos (byte offsets)
                 + (66 + 256) * 4            // start, cut
                 + (64 + 2) * 4;             // cbp, wt
    cudaFuncSetAttribute(kB, cudaFuncAttributeMaxDynamicSharedMemorySize, (int)smemB);

    // MEASUREMENT ROUND: kB launched 3x total (all idempotent & deterministic;
    // writes identical g_E each time). dur_us = base(53.6) + 2*kB.
    kS<<<BB, 1024>>>(idx);
    kB<<<dim3(NBLK, BB), KBT, smemB>>>(Wq, v_emb);
    kC<<<dim3(VV, BB), 128>>>(Wv, out);
    kB<<<dim3(NBLK, BB), KBT, smemB>>>(Wq, v_emb);   // measurement copy 1
    kB<<<dim3(NBLK, BB), KBT, smemB>>>(Wq, v_emb);   // measurement copy 2
}

// round 14
// speedup vs baseline: 1.8206x; 1.8206x over previous
#include <cuda_runtime.h>

#define BB 16
#define LL 2048
#define VV 64
#define KBT 512             // kB threads
#define NBLK 16             // kB blocks per batch (2 windows of 64 t each)
#define PADL 2560           // padded position-list length (64 classes, 8-aligned)

// Scratch (device globals)
__device__ float g_E[(size_t)BB * VV * LL];      // exp(P[b,c,t]), 8 MB
__device__ int g_pos[BB * PADL];                 // positions sorted by class, 8-aligned segs
__device__ int g_starts[BB * (VV + 1)];          // padded segment starts (8-aligned)
__device__ int g_cnt[BB * VV];                   // real counts per class

// degree-7 Taylor exp; |x| small here -> rel err < 1e-9
__device__ __forceinline__ float exp_poly(float x) {
    float r = 1.f / 5040.f;
    r = fmaf(r, x, 1.f / 720.f);
    r = fmaf(r, x, 1.f / 120.f);
    r = fmaf(r, x, 1.f / 24.f);
    r = fmaf(r, x, 1.f / 6.f);
    r = fmaf(r, x, 0.5f);
    r = fmaf(r, x, 1.f);
    r = fmaf(r, x, 1.f);
    return r;
}

#define ADD2(acc, val) asm("add.rn.f32x2 %0, %0, %1;" : "+l"(acc) : "l"(val))

// window base (in 64-t units): block bx owns windows {bx, 31-bx} -> per-block
// total work (bx+1 + 32-bx = 33) is EXACTLY equal.
__device__ __forceinline__ int win64(int wi, int bx) {
    return wi ? (31 - bx) : bx;
}

// ---------------------------------------------------------------------------
// kS: stable counting sort of positions by class (match_any), 8-aligned
// padded segments, sentinel LL. Proven ~7.5us. (R12 verbatim)
// ---------------------------------------------------------------------------
__global__ void __launch_bounds__(1024) kS(const int* __restrict__ idx) {
    __shared__ int cnt[64][65];
    __shared__ int stot[64];
    __shared__ int pstart[65];

    const int b = blockIdx.x;
    const int tid = threadIdx.x;
    const int lane = tid & 31;
    const int wid = tid >> 5;

    for (int i = tid; i < 64 * 65; i += 1024) ((int*)cnt)[i] = 0;
    __syncthreads();

    int v0, lr0, v1, lr1;
    {
        v0 = idx[b * LL + tid];
        unsigned m = __match_any_sync(0xffffffffu, v0);
        lr0 = __popc(m & ((1u << lane) - 1u));
        if (lr0 == 0) cnt[tid >> 5][v0] = __popc(m);
    }
    {
        int j = tid + 1024;
        v1 = idx[b * LL + j];
        unsigned m = __match_any_sync(0xffffffffu, v1);
        lr1 = __popc(m & ((1u << lane) - 1u));
        if (lr1 == 0) cnt[j >> 5][v1] = __popc(m);
    }
    __syncthreads();

#pragma unroll
    for (int cc = 0; cc < 2; ++cc) {
        int c = wid * 2 + cc;
        int a = cnt[2 * lane][c];
        int d = cnt[2 * lane + 1][c];
        int s = a + d;
        int x = s;
#pragma unroll
        for (int off = 1; off < 32; off <<= 1) {
            int y = __shfl_up_sync(0xffffffffu, x, off);
            if (lane >= off) x += y;
        }
        int e = x - s;
        cnt[2 * lane][c] = e;
        cnt[2 * lane + 1][c] = e + a;
        if (lane == 31) stot[c] = x;
    }
    __syncthreads();

    if (wid == 0) {
        int t0c = (stot[2 * lane] + 7) & ~7;
        int t1c = (stot[2 * lane + 1] + 7) & ~7;
        int s = t0c + t1c;
        int x = s;
#pragma unroll
        for (int off = 1; off < 32; off <<= 1) {
            int y = __shfl_up_sync(0xffffffffu, x, off);
            if (lane >= off) x += y;
        }
        int e = x - s;
        pstart[2 * lane] = e;
        pstart[2 * lane + 1] = e + t0c;
        if (lane == 31) pstart[64] = x;
    }
    __syncthreads();

    g_pos[b * PADL + pstart[v0] + cnt[tid >> 5][v0] + lr0] = tid;
    g_pos[b * PADL + pstart[v1] + cnt[(tid + 1024) >> 5][v1] + lr1] = tid + 1024;

    if (tid < 64) {
        for (int i = pstart[tid] + stot[tid]; i < pstart[tid + 1]; ++i)
            g_pos[b * PADL + i] = LL;   // sentinel
        g_cnt[b * 64 + tid] = stot[tid];
        g_starts[b * 65 + tid] = pstart[tid];
        if (tid == 0) g_starts[b * 65 + 64] = pstart[64];
    }
}

// ---------------------------------------------------------------------------
// kB v2: 256 blocks, 512 threads. Block bx: windows {bx, 31-bx} x 64 t.
//  Phase A (PAIR GATHER): warp w -> (window wi = w>>3, 8 classes vg = w&7);
//    lane = pair u in [0,32). g2[i] = (w[i-2048], w[i-2047]) with zeros
//    encoding causality exactly: gather (w[te-p], w[te+1-p]) via one LDS.64,
//    accumulate both t's with add.rn.f32x2. Sentinel p=2048 lands on zeros.
//  Phase B: 128 t x 4 cgroups, 16 classes/thread via FFMA2 (unchanged).
// ---------------------------------------------------------------------------
__global__ void __launch_bounds__(KBT, 2) kB(const float* __restrict__ Wq,
                                             const float* __restrict__ v_emb) {
    extern __shared__ __align__(16) char smraw[];
    float2* s_g2  = (float2*)smraw;                      // 4096 pairs (32KB)
    float*  s_w   = (float*)(smraw + 4096 * 8);          // 2048 compact w
    float*  s_wq  = s_w + LL;                            // 4096
    float*  s_l1  = s_wq + VV * VV;                      // VV*128 = 8192, [v][tt]
    float*  s_invd = s_l1 + VV * 128;                    // 128 (8B aligned)
    int*    s_pos = (int*)(s_invd + 128);                // PADL (byte offsets p<<3)
    int*    s_start = s_pos + PADL;                      // 66
    int*    s_cut   = s_start + 66;                      // 2*64 (window, class)
    float*  s_cbp   = (float*)(s_cut + 128);             // 64 inclusive chunk prefix
    float*  s_wt    = s_cbp + 64;                        // 2
    float*  s_wt2   = s_wt + 2;                          // 2
    float*  wf = (float*)s_g2;

    const int bx  = blockIdx.x;                          // 0..15
    const int b   = blockIdx.y;
    const int tid = threadIdx.x;
    const int lane = tid & 31;

    // pass 1: g2.x components + compact w
    for (int i = tid; i < 4096; i += KBT) {
        float val = 0.f;
        if (i >= 2048) { val = exp_poly(v_emb[i - 2048]); s_w[i - 2048] = val; }
        wf[2 * i] = val;
    }
    for (int i = tid; i < VV * VV; i += KBT) s_wq[i] = Wq[i];
    {   // positions staged pre-scaled by 8 (byte offset into float2 table)
        const int4* src = (const int4*)(g_pos + b * PADL);
        int4* dst = (int4*)s_pos;
        for (int i = tid; i < PADL / 4; i += KBT) {
            int4 p = src[i];
            p.x <<= 3; p.y <<= 3; p.z <<= 3; p.w <<= 3;
            dst[i] = p;
        }
    }
    for (int i = tid; i <= VV; i += KBT) s_start[i] = g_starts[b * 65 + i];
    __syncthreads();

    // pass 2: g2.y[i] = g2.x[i+1] (reads even slots only, writes odd: no race)
    for (int i = tid; i < 4096; i += KBT)
        wf[2 * i + 1] = (i + 1 < 4096) ? wf[2 * (i + 1)] : 0.f;

    // cutoffs: tid<128 -> (wi = tid>>6, v = tid&63)
    if (tid < 128) {
        const int wi = tid >> 6;
        const int v  = tid & 63;
        const int te8 = ((win64(wi, bx) + 1) * 64) << 3;
        int lo = s_start[v], hi = s_start[v + 1];
        while (lo < hi) {
            int mid = (lo + hi) >> 1;
            if (s_pos[mid] < te8) lo = mid + 1; else hi = mid;
        }
        s_cut[tid] = lo;
    }
    // 32-elem chunk sums of w (64 chunks); lane-rotated reads = conflict-free
    float cbx = 0.f;
    if (tid < 64) {
        float cb = 0.f;
        const int cb0 = tid * 32;
#pragma unroll
        for (int m = 0; m < 32; ++m) cb += s_w[cb0 + ((m + lane) & 31)];
        cbx = cb;
#pragma unroll
        for (int off = 1; off < 32; off <<= 1) {
            float y = __shfl_up_sync(0xffffffffu, cbx, off);
            if (lane >= off) cbx += y;
        }
        if (lane == 31) s_wt[tid >> 5] = cbx;
    }
    // intra-window scans: tid<128 -> (wi = tid>>6, off = tid&63)
    float sv = 0.f;
    if (tid < 128) {
        const int wi = tid >> 6;
        const int off = tid & 63;
        sv = s_w[win64(wi, bx) * 64 + off];
#pragma unroll
        for (int o = 1; o < 32; o <<= 1) {
            float y = __shfl_up_sync(0xffffffffu, sv, o);
            if (lane >= o) sv += y;
        }
        if (lane == 31 && (off >> 5) == 0) s_wt2[wi] = sv;  // first-half totals
    }
    __syncthreads();
    if (tid < 64) s_cbp[tid] = cbx + ((tid >> 5) ? s_wt[0] : 0.f);
    __syncthreads();
    if (tid < 128) {
        const int wi = tid >> 6;
        const int off = tid & 63;
        const int cb = win64(wi, bx) * 2;    // 32-chunks before window
        float D = (cb ? s_cbp[cb - 1] : 0.f) + sv + ((off >> 5) ? s_wt2[wi] : 0.f);
        s_invd[tid] = 1.0f / D;
    }
    __syncthreads();

    // --- Phase A: pair gather. warp w -> (wi = w>>3, vg = w&7), lane = pair ---
    {
        const int w  = tid >> 5;
        const int wi = w >> 3;               // 0..1
        const int vg = w & 7;                // 0..7
        const int te = win64(wi, bx) * 64 + 2 * lane;
        const char* wtb = (const char*)(s_g2 + 2048 + te);   // gather at wtb - p8
        const unsigned long long iv2 =
            *(const unsigned long long*)&s_invd[wi * 64 + 2 * lane];
        const int4* P = (const int4*)s_pos;
#pragma unroll
        for (int vs = 0; vs < 8; ++vs) {
            const int v = vg + 8 * vs;
            int g    = s_start[v] >> 3;      // segments 8-aligned
            int gend = (s_cut[wi * 64 + v] + 7) >> 3;  // extras hit zeros
            unsigned long long a0 = 0ull, a1 = 0ull, a2 = 0ull, a3 = 0ull;
#pragma unroll 2
            for (; g < gend; ++g) {
                int4 pa = P[2 * g];
                int4 pb = P[2 * g + 1];
                ADD2(a0, *(const unsigned long long*)(wtb - pa.x));
                ADD2(a1, *(const unsigned long long*)(wtb - pa.y));
                ADD2(a2, *(const unsigned long long*)(wtb - pa.z));
                ADD2(a3, *(const unsigned long long*)(wtb - pa.w));
                ADD2(a0, *(const unsigned long long*)(wtb - pb.x));
                ADD2(a1, *(const unsigned long long*)(wtb - pb.y));
                ADD2(a2, *(const unsigned long long*)(wtb - pb.z));
                ADD2(a3, *(const unsigned long long*)(wtb - pb.w));
            }
            ADD2(a0, a1); ADD2(a2, a3); ADD2(a0, a2);
            unsigned long long res;
            asm("mul.rn.f32x2 %0, %1, %2;" : "=l"(res) : "l"(a0), "l"(iv2));
            *(unsigned long long*)&s_l1[v * 128 + wi * 64 + 2 * lane] = res;
        }
    }
    __syncthreads();

    // --- Phase B: 16 classes per thread (tt = tid&127, cg = tid>>7), FFMA2 ---
    const int tt = tid & 127;
    const int cg = tid >> 7;            // 0..3
    unsigned long long acc[8];
#pragma unroll
    for (int i = 0; i < 8; ++i) acc[i] = 0ull;

#pragma unroll 4
    for (int v = 0; v < VV; ++v) {
        float lv = s_l1[v * 128 + tt];
        unsigned long long lv2;
        asm("mov.b64 %0, {%1, %1};" : "=l"(lv2) : "r"(__float_as_uint(lv)));
        const double2* q = (const double2*)&s_wq[v * VV + cg * 16];
#pragma unroll
        for (int i = 0; i < 4; ++i) {
            double2 qq = q[i];
            unsigned long long qa = __double_as_longlong(qq.x);
            unsigned long long qb = __double_as_longlong(qq.y);
            asm("fma.rn.f32x2 %0, %1, %2, %0;" : "+l"(acc[2 * i])     : "l"(qa), "l"(lv2));
            asm("fma.rn.f32x2 %0, %1, %2, %0;" : "+l"(acc[2 * i + 1]) : "l"(qb), "l"(lv2));
        }
    }

    // Epilogue: E = exp(P), coalesced over t within each window
    const int t_out = win64(tt >> 6, bx) * 64 + (tt & 63);
    float* eb = g_E + ((size_t)b * VV + cg * 16) * LL + t_out;
#pragma unroll
    for (int i = 0; i < 8; ++i) {
        unsigned lo, hi;
        asm("mov.b64 {%0, %1}, %2;" : "=r"(lo), "=r"(hi) : "l"(acc[i]));
        eb[(size_t)(2 * i) * LL]     = exp_poly(__uint_as_float(lo));
        eb[(size_t)(2 * i + 1) * LL] = exp_poly(__uint_as_float(hi));
    }
}

// ---------------------------------------------------------------------------
// kC: per (b,c), 128 threads (R12 verbatim).
// ---------------------------------------------------------------------------
__global__ void __launch_bounds__(128) kC(const float* __restrict__ Wv,
                                          float* __restrict__ out) {
    __shared__ __align__(16) float sE[LL];
    __shared__ float sP[LL];
    __shared__ __align__(16) int spos[PADL];
    __shared__ int sstart[VV + 2];
    __shared__ int scnt[VV];
    __shared__ float wtot[4];

    const int c   = blockIdx.x;
    const int b   = blockIdx.y;
    const int tid = threadIdx.x;
    const int lane = tid & 31, w = tid >> 5;

    const float* Ep = g_E + ((size_t)b * VV + c) * LL;
    {
        const float4* src = (const float4*)Ep;
        float4* dst = (float4*)sE;
        for (int i = tid; i < LL / 4; i += 128) dst[i] = src[i];
        const int4* psrc = (const int4*)(g_pos + b * PADL);
        int4* pdst = (int4*)spos;
        for (int i = tid; i < PADL / 4; i += 128) pdst[i] = psrc[i];
    }
    for (int i = tid; i <= VV; i += 128) sstart[i] = g_starts[b * 65 + i];
    if (tid < 64) scnt[tid] = g_cnt[b * 64 + tid];
    __syncthreads();

    const int s0 = tid * 16;
    float tot = 0.f;
#pragma unroll
    for (int m = 0; m < 16; ++m) tot += sE[s0 + m];
    float x = tot;
#pragma unroll
    for (int off = 1; off < 32; off <<= 1) {
        float y = __shfl_up_sync(0xffffffffu, x, off);
        if (lane >= off) x += y;
    }
    if (lane == 31) wtot[w] = x;
    __syncthreads();
    float base = x - tot;
    for (int j = 0; j < w; ++j) base += wtot[j];
#pragma unroll
    for (int m = 0; m < 16; ++m) { base += sE[s0 + m]; sP[s0 + m] = base; }
    __syncthreads();

    if (tid < 64) {
        const float wv00 = Wv[0];
        float* ob = out + (size_t)b * LL * VV;

        int ptr  = sstart[tid];
        const int pend = ptr + scnt[tid];
        float acc = 0.f;

        const int cbeg = sstart[c];
        const int cend = cbeg + scnt[c];
        for (int k = cbeg; k < cend; ++k) {
            const int tk = spos[k];
            while (ptr < pend) {
                int p = spos[ptr];
                if (p > tk) break;
                acc += sE[p];
                ++ptr;
            }
            float sc = __fdividef(wv00, sP[tk]);
            ob[(size_t)tk * VV + tid] = acc * sc;
        }
    }
}

extern "C" void kernel_launch(void* const* d_in, const int* in_sizes, int n_in,
                              void* d_out, int out_size) {
    const int*   idx   = (const int*)d_in[0];
    const float* Wq    = (const float*)d_in[1];
    const float* Wv    = (const float*)d_in[2];
    const float* v_emb = (const float*)d_in[3];
    float* out = (float*)d_out;

    size_t smemB = 4096 * 8                      // g2
                 + (size_t)LL * 4                // compact w
                 + (size_t)VV * VV * 4           // wq
                 + (size_t)VV * 128 * 4          // l1
                 + 128 * 4                       // invd
                 + (size_t)PADL * 4              // pos (byte offsets)
                 + (66 + 128) * 4                // start, cut
                 + (64 + 2 + 2) * 4;             // cbp, wt, wt2
    cudaFuncSetAttribute(kB, cudaFuncAttributeMaxDynamicSharedMemorySize, (int)smemB);

    kS<<<BB, 1024>>>(idx);
    kB<<<dim3(NBLK, BB), KBT, smemB>>>(Wq, v_emb);
    kC<<<dim3(VV, BB), 128>>>(Wv, out);
}

// round 15
// speedup vs baseline: 1.9719x; 1.0831x over previous
#include <cuda_runtime.h>

#define BB 16
#define LL 2048
#define VV 64
#define KBT 512             // kB threads: 128 t x 4 vgroups
#define NBLK 16             // kB blocks per batch (4 windows of 32 t each)
#define PADL 2560           // padded position-list length (64 classes, 8-aligned)

// Scratch (device globals)
__device__ float g_E[(size_t)BB * VV * LL];      // exp(P[b,c,t]), 8 MB
__device__ int g_pos[BB * PADL];                 // positions sorted by class, 8-aligned segs
__device__ int g_starts[BB * (VV + 1)];          // padded segment starts (8-aligned)
__device__ int g_cnt[BB * VV];                   // real counts per class

// degree-7 Taylor exp; |x| small here -> rel err < 1e-9
__device__ __forceinline__ float exp_poly(float x) {
    float r = 1.f / 5040.f;
    r = fmaf(r, x, 1.f / 720.f);
    r = fmaf(r, x, 1.f / 120.f);
    r = fmaf(r, x, 1.f / 24.f);
    r = fmaf(r, x, 1.f / 6.f);
    r = fmaf(r, x, 0.5f);
    r = fmaf(r, x, 1.f);
    r = fmaf(r, x, 1.f);
    return r;
}

// window base (in 32-t units) for window-slot wi of block bx:
// {bx, 31-bx, 32+bx, 63-bx} -> per-block total work is EXACTLY equal.
__device__ __forceinline__ int win32(int wi, int bx) {
    int base = (wi & 2) ? 32 : 0;
    return (wi & 1) ? (base + 31 - bx) : (base + bx);
}

// ---------------------------------------------------------------------------
// kS: stable counting sort of positions by class (match_any), 8-aligned
// padded segments, sentinel LL. Proven ~7.5us. (R12 verbatim)
// ---------------------------------------------------------------------------
__global__ void __launch_bounds__(1024) kS(const int* __restrict__ idx) {
    __shared__ int cnt[64][65];
    __shared__ int stot[64];
    __shared__ int pstart[65];

    const int b = blockIdx.x;
    const int tid = threadIdx.x;
    const int lane = tid & 31;
    const int wid = tid >> 5;

    for (int i = tid; i < 64 * 65; i += 1024) ((int*)cnt)[i] = 0;
    __syncthreads();

    int v0, lr0, v1, lr1;
    {
        v0 = idx[b * LL + tid];
        unsigned m = __match_any_sync(0xffffffffu, v0);
        lr0 = __popc(m & ((1u << lane) - 1u));
        if (lr0 == 0) cnt[tid >> 5][v0] = __popc(m);
    }
    {
        int j = tid + 1024;
        v1 = idx[b * LL + j];
        unsigned m = __match_any_sync(0xffffffffu, v1);
        lr1 = __popc(m & ((1u << lane) - 1u));
        if (lr1 == 0) cnt[j >> 5][v1] = __popc(m);
    }
    __syncthreads();

#pragma unroll
    for (int cc = 0; cc < 2; ++cc) {
        int c = wid * 2 + cc;
        int a = cnt[2 * lane][c];
        int d = cnt[2 * lane + 1][c];
        int s = a + d;
        int x = s;
#pragma unroll
        for (int off = 1; off < 32; off <<= 1) {
            int y = __shfl_up_sync(0xffffffffu, x, off);
            if (lane >= off) x += y;
        }
        int e = x - s;
        cnt[2 * lane][c] = e;
        cnt[2 * lane + 1][c] = e + a;
        if (lane == 31) stot[c] = x;
    }
    __syncthreads();

    if (wid == 0) {
        int t0c = (stot[2 * lane] + 7) & ~7;
        int t1c = (stot[2 * lane + 1] + 7) & ~7;
        int s = t0c + t1c;
        int x = s;
#pragma unroll
        for (int off = 1; off < 32; off <<= 1) {
            int y = __shfl_up_sync(0xffffffffu, x, off);
            if (lane >= off) x += y;
        }
        int e = x - s;
        pstart[2 * lane] = e;
        pstart[2 * lane + 1] = e + t0c;
        if (lane == 31) pstart[64] = x;
    }
    __syncthreads();

    g_pos[b * PADL + pstart[v0] + cnt[tid >> 5][v0] + lr0] = tid;
    g_pos[b * PADL + pstart[v1] + cnt[(tid + 1024) >> 5][v1] + lr1] = tid + 1024;

    if (tid < 64) {
        for (int i = pstart[tid] + stot[tid]; i < pstart[tid + 1]; ++i)
            g_pos[b * PADL + i] = LL;   // sentinel
        g_cnt[b * 64 + tid] = stot[tid];
        g_starts[b * 65 + tid] = pstart[tid];
        if (tid == 0) g_starts[b * 65 + 64] = pstart[64];
    }
}

// ---------------------------------------------------------------------------
// kB: R12 verbatim (measured 24.9us) — 256 blocks, 512 threads, exact
// window balancing {bx, 31-bx, 32+bx, 63-bx}, byte-offset gather, FFMA2.
// ---------------------------------------------------------------------------
__global__ void __launch_bounds__(KBT, 2) kB(const float* __restrict__ Wq,
                                             const float* __restrict__ v_emb) {
    extern __shared__ __align__(16) char smraw[];
    float* s_wg   = (float*)smraw;                       // 2*LL: guard zeros + w
    float* s_wq   = s_wg + 2 * LL;                       // 4096 f
    float* s_l1   = s_wq + VV * VV;                      // VV*128 = 8192 f
    float* s_invd = s_l1 + VV * 128;                     // 128 (indexed by tt)
    int*   s_pos  = (int*)(s_invd + 128);                // PADL (byte offsets p<<2)
    int*   s_start = s_pos + PADL;                       // 66
    int*   s_cut   = s_start + 66;                       // 4*64 (per window, class)
    float* s_cbp   = (float*)(s_cut + 256);              // 64 inclusive chunk prefix
    float* s_wt    = s_cbp + 64;                         // 2
    float* s_w = s_wg + LL;

    const int bx  = blockIdx.x;                          // 0..15
    const int b   = blockIdx.y;
    const int tid = threadIdx.x;
    const int lane = tid & 31;

    for (int i = tid; i < LL; i += KBT) { s_wg[i] = 0.f; s_w[i] = exp_poly(v_emb[i]); }
    for (int i = tid; i < VV * VV; i += KBT) s_wq[i] = Wq[i];
    {   // positions staged pre-scaled by 4 (byte offsets)
        const int4* src = (const int4*)(g_pos + b * PADL);
        int4* dst = (int4*)s_pos;
        for (int i = tid; i < PADL / 4; i += KBT) {
            int4 p = src[i];
            p.x <<= 2; p.y <<= 2; p.z <<= 2; p.w <<= 2;
            dst[i] = p;
        }
    }
    for (int i = tid; i <= VV; i += KBT) s_start[i] = g_starts[b * 65 + i];
    __syncthreads();

    // cutoffs: tid<256 -> (wi = tid>>6, v = tid&63)
    if (tid < 256) {
        const int wi = tid >> 6;
        const int v  = tid & 63;
        const int te4 = ((win32(wi, bx) + 1) * 32) << 2;
        int lo = s_start[v], hi = s_start[v + 1];
        while (lo < hi) {
            int mid = (lo + hi) >> 1;
            if (s_pos[mid] < te4) lo = mid + 1; else hi = mid;
        }
        s_cut[tid] = lo;
    }
    // 32-elem chunk sums of w (64 chunks), scanned with 2 warps + combine
    float cbx = 0.f;
    if (tid < 64) {
        float cb = 0.f;
        const int cb0 = tid * 32;
#pragma unroll
        for (int m = 0; m < 32; ++m) cb += s_w[cb0 + m];
        cbx = cb;
#pragma unroll
        for (int off = 1; off < 32; off <<= 1) {
            float y = __shfl_up_sync(0xffffffffu, cbx, off);
            if (lane >= off) cbx += y;
        }
        if (lane == 31) s_wt[tid >> 5] = cbx;
    }
    __syncthreads();
    if (tid < 64) s_cbp[tid] = cbx + ((tid >> 5) ? s_wt[0] : 0.f);
    __syncthreads();
    if (tid < 128) {
        const int wi = tid >> 5;
        const int wb = win32(wi, bx);           // chunk index = window base/32
        float sv = s_w[wb * 32 + lane];
#pragma unroll
        for (int off = 1; off < 32; off <<= 1) {
            float y = __shfl_up_sync(0xffffffffu, sv, off);
            if (lane >= off) sv += y;
        }
        float D = (wb ? s_cbp[wb - 1] : 0.f) + sv;
        s_invd[tid] = 1.0f / D;
    }
    __syncthreads();

    // --- Phase A: warp w -> (window wi = w>>2, vgroup vg = w&3) ---
    {
        const int w  = tid >> 5;
        const int wi = w >> 2;
        const int vg = w & 3;
        const int tt = wi * 32 + lane;
        const int t  = win32(wi, bx) * 32 + lane;
        const float invd = s_invd[tt];
        const char* wtb = (const char*)(s_w + t);   // w[t-p] at wtb - 4p
        const int4* P = (const int4*)s_pos;
#pragma unroll
        for (int vs = 0; vs < 16; ++vs) {
            const int v = vg + 4 * vs;
            int g    = s_start[v] >> 3;             // segments 8-aligned
            int gend = (s_cut[wi * 64 + v] + 7) >> 3;  // tail extras hit zero guard
            float a0 = 0.f, a1 = 0.f, a2 = 0.f, a3 = 0.f;
#pragma unroll 2
            for (; g < gend; ++g) {
                int4 pa = P[2 * g];
                int4 pb = P[2 * g + 1];
                a0 += *(const float*)(wtb - pa.x);
                a1 += *(const float*)(wtb - pa.y);
                a2 += *(const float*)(wtb - pa.z);
                a3 += *(const float*)(wtb - pa.w);
                a0 += *(const float*)(wtb - pb.x);
                a1 += *(const float*)(wtb - pb.y);
                a2 += *(const float*)(wtb - pb.z);
                a3 += *(const float*)(wtb - pb.w);
            }
            s_l1[v * 128 + tt] = ((a0 + a1) + (a2 + a3)) * invd;
        }
    }
    __syncthreads();

    // --- Phase B: 16 classes per thread (tt = tid&127, cg = tid>>7), FFMA2 ---
    const int tt = tid & 127;
    const int cg = tid >> 7;            // 0..3
    unsigned long long acc[8];
#pragma unroll
    for (int i = 0; i < 8; ++i) acc[i] = 0ull;

#pragma unroll 4
    for (int v = 0; v < VV; ++v) {
        float lv = s_l1[v * 128 + tt];
        unsigned long long lv2;
        asm("mov.b64 %0, {%1, %1};" : "=l"(lv2) : "r"(__float_as_uint(lv)));
        const double2* q = (const double2*)&s_wq[v * VV + cg * 16];
#pragma unroll
        for (int i = 0; i < 4; ++i) {
            double2 qq = q[i];
            unsigned long long qa = __double_as_longlong(qq.x);
            unsigned long long qb = __double_as_longlong(qq.y);
            asm("fma.rn.f32x2 %0, %1, %2, %0;" : "+l"(acc[2 * i])     : "l"(qa), "l"(lv2));
            asm("fma.rn.f32x2 %0, %1, %2, %0;" : "+l"(acc[2 * i + 1]) : "l"(qb), "l"(lv2));
        }
    }

    // Epilogue: E = exp(P), coalesced over t within each window
    const int t_out = win32(tt >> 5, bx) * 32 + (tt & 31);
    float* eb = g_E + ((size_t)b * VV + cg * 16) * LL + t_out;
#pragma unroll
    for (int i = 0; i < 8; ++i) {
        unsigned lo, hi;
        asm("mov.b64 {%0, %1}, %2;" : "=r"(lo), "=r"(hi) : "l"(acc[i]));
        eb[(size_t)(2 * i) * LL]     = exp_poly(__uint_as_float(lo));
        eb[(size_t)(2 * i + 1) * LL] = exp_poly(__uint_as_float(hi));
    }
}

// ---------------------------------------------------------------------------
// kC v2: per (b,c), 128 threads. CONFLICT-FREE prefix sum:
//   - strip sums read straight from gmem/L2 into 16 registers (LDG.128 x4,
//     coalesced) — no 16-way-conflicted LDS passes
//   - inclusive prefix written to SWIZZLED sP: phys = i + (i>>4) -> store
//     addresses tid*17 + m, banks all distinct (17 odd) -> conflict-free
//   - walk reads sP[tk + (tk>>4)]
// ---------------------------------------------------------------------------
__global__ void __launch_bounds__(128) kC(const float* __restrict__ Wv,
                                          float* __restrict__ out) {
    __shared__ __align__(16) float sE[LL];
    __shared__ float sPs[128 * 17];      // swizzled inclusive prefix of E
    __shared__ __align__(16) int spos[PADL];
    __shared__ int sstart[VV + 2];
    __shared__ int scnt[VV];
    __shared__ float wtot[4];

    const int c   = blockIdx.x;
    const int b   = blockIdx.y;
    const int tid = threadIdx.x;
    const int lane = tid & 31, w = tid >> 5;

    const float* Ep = g_E + ((size_t)b * VV + c) * LL;
    {
        const float4* src = (const float4*)Ep;
        float4* dst = (float4*)sE;
        for (int i = tid; i < LL / 4; i += 128) dst[i] = src[i];
        const int4* psrc = (const int4*)(g_pos + b * PADL);
        int4* pdst = (int4*)spos;
        for (int i = tid; i < PADL / 4; i += 128) pdst[i] = psrc[i];
    }
    for (int i = tid; i <= VV; i += 128) sstart[i] = g_starts[b * 65 + i];
    if (tid < 64) scnt[tid] = g_cnt[b * 64 + tid];

    // strip of 16 from GMEM into registers (coalesced 64B per lane)
    float ev[16];
    float tot = 0.f;
    {
        const float4* s4 = (const float4*)(Ep + tid * 16);
#pragma unroll
        for (int k = 0; k < 4; ++k) {
            float4 q = s4[k];
            ev[4 * k + 0] = q.x; ev[4 * k + 1] = q.y;
            ev[4 * k + 2] = q.z; ev[4 * k + 3] = q.w;
            tot += (q.x + q.y) + (q.z + q.w);
        }
    }
    float x = tot;
#pragma unroll
    for (int off = 1; off < 32; off <<= 1) {
        float y = __shfl_up_sync(0xffffffffu, x, off);
        if (lane >= off) x += y;
    }
    if (lane == 31) wtot[w] = x;
    __syncthreads();
    float run = x - tot;
    for (int j = 0; j < w; ++j) run += wtot[j];
    {   // conflict-free swizzled stores: phys = tid*17 + m
        float* p = sPs + tid * 17;
#pragma unroll
        for (int m = 0; m < 16; ++m) { run += ev[m]; p[m] = run; }
    }
    __syncthreads();

    if (tid < 64) {
        const float wv00 = Wv[0];
        float* ob = out + (size_t)b * LL * VV;

        int ptr  = sstart[tid];
        const int pend = ptr + scnt[tid];
        float acc = 0.f;

        const int cbeg = sstart[c];
        const int cend = cbeg + scnt[c];
        for (int k = cbeg; k < cend; ++k) {
            const int tk = spos[k];
            while (ptr < pend) {
                int p = spos[ptr];
                if (p > tk) break;
                acc += sE[p];
                ++ptr;
            }
            float sc = __fdividef(wv00, sPs[tk + (tk >> 4)]);
            ob[(size_t)tk * VV + tid] = acc * sc;
        }
    }
}

extern "C" void kernel_launch(void* const* d_in, const int* in_sizes, int n_in,
                              void* d_out, int out_size) {
    const int*   idx   = (const int*)d_in[0];
    const float* Wq    = (const float*)d_in[1];
    const float* Wv    = (const float*)d_in[2];
    const float* v_emb = (const float*)d_in[3];
    float* out = (float*)d_out;

    size_t smemB = (size_t)(2 * LL) * 4      // guard + w
                 + (size_t)VV * VV * 4       // wq
                 + (size_t)VV * 128 * 4      // l1
                 + 128 * 4                   // invd
                 + (size_t)PADL * 4          // pos (byte offsets)
                 + (66 + 256) * 4            // start, cut
                 + (64 + 2) * 4;             // cbp, wt
    cudaFuncSetAttribute(kB, cudaFuncAttributeMaxDynamicSharedMemorySize, (int)smemB);

    kS<<<BB, 1024>>>(idx);
    kB<<<dim3(NBLK, BB), KBT, smemB>>>(Wq, v_emb);
    kC<<<dim3(VV, BB), 128>>>(Wv, out);
}